// round 9
// baseline (speedup 1.0000x reference)
#include <cuda_runtime.h>
#include <cuda_bf16.h>
#include <cstdint>

// MultiGridAgentEncoder: fused slot-gather + relu(x @ W + b)
// R9: warp-specialized persistent kernel (R8) with single merged k-loop in the
// consumer: each A/B fragment loaded exactly once per k-step (12 ldsm vs 18).

#define NTHREADS 512
#define GRID     148
#define NTILES   2048
#define PITCH    272          // bytes per K-row (128 bf16 + 16B pad), ldmatrix conflict-free

// smem byte offsets
#define SM_A0_HI 0
#define SM_A0_LO 17408
#define SM_A1_HI 34816
#define SM_A1_LO 52224
#define SM_B_HI  69632        // 256*272 = 69632, ends 139264
#define SM_B_LO  139264       // ends 208896
#define SM_SLOT  208896       // 2 bufs * 8*64 bytes = 1024, ends 209920
#define SMEM_BYTES 209920

// Pre-split W (filled once by w_split): [n][k] bf16, k padded to 128
__device__ __nv_bfloat16 g_Whi[256 * 128];
__device__ __nv_bfloat16 g_Wlo[256 * 128];

__global__ void w_split(const float* __restrict__ W) {
    const int k = blockIdx.x;        // 0..127
    const int n = threadIdx.x;       // 0..255
    float w = (k < 117) ? W[k * 256 + n] : 0.0f;
    __nv_bfloat16 h = __float2bfloat16(w);
    g_Whi[n * 128 + k] = h;
    g_Wlo[n * 128 + k] = __float2bfloat16(w - __bfloat162float(h));
}

static __device__ __forceinline__ uint32_t smem_u32(const void* p) {
    uint32_t a;
    asm("{ .reg .u64 t; cvta.to.shared.u64 t, %1; cvt.u32.u64 %0, t; }" : "=r"(a) : "l"(p));
    return a;
}
static __device__ __forceinline__ void bar_sync(int id, int cnt) {
    asm volatile("bar.sync %0, %1;" :: "r"(id), "r"(cnt) : "memory");
}
static __device__ __forceinline__ void bar_arrive(int id, int cnt) {
    asm volatile("bar.arrive %0, %1;" :: "r"(id), "r"(cnt) : "memory");
}
static __device__ __forceinline__ void ldsm_x4(uint32_t& r0, uint32_t& r1, uint32_t& r2,
                                               uint32_t& r3, uint32_t addr) {
    asm volatile("ldmatrix.sync.aligned.m8n8.x4.shared.b16 {%0,%1,%2,%3}, [%4];"
                 : "=r"(r0), "=r"(r1), "=r"(r2), "=r"(r3) : "r"(addr));
}
static __device__ __forceinline__ void mma_bf16(float* c, const uint32_t* a,
                                                uint32_t b0, uint32_t b1) {
    asm volatile(
        "mma.sync.aligned.m16n8k16.row.col.f32.bf16.bf16.f32 "
        "{%0,%1,%2,%3}, {%4,%5,%6,%7}, {%8,%9}, {%0,%1,%2,%3};"
        : "+f"(c[0]), "+f"(c[1]), "+f"(c[2]), "+f"(c[3])
        : "r"(a[0]), "r"(a[1]), "r"(a[2]), "r"(a[3]), "r"(b0), "r"(b1));
}
static __device__ __forceinline__ void splitw(float v, __nv_bfloat16& h, __nv_bfloat16& l) {
    h = __float2bfloat16(v);
    l = __float2bfloat16(v - __bfloat162float(h));
}
// write 13 features (hi/lo split) for one A row starting at k0
static __device__ __forceinline__ void write13(char* ah, char* al, int k0, const float* f) {
#pragma unroll
    for (int j = 0; j < 13; j++) {
        __nv_bfloat16 h, l; splitw(f[j], h, l);
        *(__nv_bfloat16*)(ah + (k0 + j) * 2) = h;
        *(__nv_bfloat16*)(al + (k0 + j) * 2) = l;
    }
}

__global__ __launch_bounds__(512, 1)
void mg_enc_ws(const float* __restrict__ qpos, const float* __restrict__ qdir,
               const float* __restrict__ qab,  const float* __restrict__ qcar,
               const float* __restrict__ qst,
               const float* __restrict__ apos, const float* __restrict__ adir,
               const float* __restrict__ aab,  const float* __restrict__ acar,
               const float* __restrict__ ast,
               const int*   __restrict__ color,
               const float* __restrict__ bias,
               float* __restrict__ out)
{
    extern __shared__ __align__(128) char smem[];
    const uint32_t sbase = smem_u32(smem);
    const int tid = threadIdx.x;

    if (tid >= 256) {
        // ======================= PRODUCER (warps 8..15) =======================
        const int tp = tid - 256;

        // zero-pad K rows 117..127 in all 4 A buffers (done once)
        for (int idx = tp; idx < 64 * 11; idx += 256) {
            const int r = idx / 11, kk = 117 + idx % 11;
            const uint32_t o = r * PITCH + kk * 2;
            *(__nv_bfloat16*)(smem + SM_A0_HI + o) = __nv_bfloat16(0.0f);
            *(__nv_bfloat16*)(smem + SM_A0_LO + o) = __nv_bfloat16(0.0f);
            *(__nv_bfloat16*)(smem + SM_A1_HI + o) = __nv_bfloat16(0.0f);
            *(__nv_bfloat16*)(smem + SM_A1_LO + o) = __nv_bfloat16(0.0f);
        }

        int t = blockIdx.x;
        int4 c0, c1, c2, c3;
        if (tp < 64) {
            const int4* cp = (const int4*)(color + (size_t)(t * 64 + tp) * 16);
            c0 = cp[0]; c1 = cp[1]; c2 = cp[2]; c3 = cp[3];
        }

        for (int it = 0; t < NTILES; it++, t += GRID) {
            const int buf = it & 1;
            if (it >= 2) bar_sync(3 + buf, 512);              // wait buf free

            signed char* slotb = (signed char*)(smem + SM_SLOT) + buf * 512;
            if (tp < 64) {
                int cols[16] = { c0.x, c0.y, c0.z, c0.w, c1.x, c1.y, c1.z, c1.w,
                                 c2.x, c2.y, c2.z, c2.w, c3.x, c3.y, c3.z, c3.w };
                signed char sa[8];
#pragma unroll
                for (int s = 0; s < 8; s++) sa[s] = -1;
                int sg = 0, sy = 0;
#pragma unroll
                for (int n = 0; n < 16; n++) {
                    int c = cols[n];
                    if (c == 5) { if (sg < 4) sa[sg] = (signed char)n; sg++; }
                    else if (c == 4) { if (sy < 4) sa[4 + sy] = (signed char)n; sy++; }
                }
#pragma unroll
                for (int s = 0; s < 8; s++) slotb[s * 64 + tp] = sa[s];
            }
            bar_sync(5, 256);                                  // producers: slots visible

            // prefetch next tile's color rows
            const int tn = t + GRID;
            if (tp < 64 && tn < NTILES) {
                const int4* cp = (const int4*)(color + (size_t)(tn * 64 + tp) * 16);
                c0 = cp[0]; c1 = cp[1]; c2 = cp[2]; c3 = cp[3];
            }

            char* const ahB = smem + (buf ? SM_A1_HI : SM_A0_HI);
            char* const alB = smem + (buf ? SM_A1_LO : SM_A0_LO);
            const int row0 = t * 64;

            // query features -> k 0..12 (64 threads, one per row)
            if (tp < 64) {
                const size_t row = (size_t)(row0 + tp);
                float f[13];
                *(float2*)(f + 0) = *(const float2*)(qpos + row * 2);
                *(float4*)(f + 2) = *(const float4*)(qdir + row * 4);
                *(float2*)(f + 6) = *(const float2*)(qab  + row * 2);
                *(float2*)(f + 8) = *(const float2*)(qcar + row * 2);
                f[10] = qst[row * 3 + 0]; f[11] = qst[row * 3 + 1]; f[12] = qst[row * 3 + 2];
                write13(ahB + tp * PITCH, alB + tp * PITCH, 0, f);
            }

            // agent gather: unit = (row, slot); 2 units per thread
#pragma unroll
            for (int uu = 0; uu < 2; uu++) {
                const int u = tp * 2 + uu;
                const int r = u >> 3, s = u & 7;
                const int a = (int)slotb[s * 64 + r];
                float f[13];
                if (a >= 0) {
                    const size_t base = (size_t)(row0 + r) * 16 + a;
                    *(float2*)(f + 0) = *(const float2*)(apos + base * 2);
                    *(float4*)(f + 2) = *(const float4*)(adir + base * 4);
                    *(float2*)(f + 6) = *(const float2*)(aab  + base * 2);
                    *(float2*)(f + 8) = *(const float2*)(acar + base * 2);
                    f[10] = ast[base * 3 + 0]; f[11] = ast[base * 3 + 1]; f[12] = ast[base * 3 + 2];
                } else {
#pragma unroll
                    for (int j = 0; j < 13; j++) f[j] = 0.0f;
                }
                write13(ahB + r * PITCH, alB + r * PITCH, 13 + s * 13, f);
            }
            bar_arrive(1 + buf, 512);                          // A[buf] ready
        }
    } else {
        // ======================= CONSUMER (warps 0..7) =======================
        const int wid = tid >> 5, lid = tid & 31;

        // B tiles: copy pre-split bf16 W into smem (once)
#pragma unroll
        for (int it = 0; it < 16; it++) {
            const int idx = it * 256 + tid;
            const int n = idx >> 4, c = idx & 15;
            *(uint4*)(smem + SM_B_HI + n * PITCH + c * 16) =
                *(const uint4*)((const char*)g_Whi + n * 256 + c * 16);
            *(uint4*)(smem + SM_B_LO + n * PITCH + c * 16) =
                *(const uint4*)((const char*)g_Wlo + n * 256 + c * 16);
        }

        const int wm = wid >> 2, wn = wid & 3;   // 2 x 4 warp grid, warp tile 32x64
        const uint32_t lrow = lid & 15, lhalf = (uint32_t)lid >> 4;
        const uint32_t a_lane = (wm * 32 + lrow) * PITCH + lhalf * 16;
        const uint32_t b_lane = (wn * 64 + lrow) * PITCH + lhalf * 16;
        const uint32_t BHb = sbase + SM_B_HI + b_lane;
        const uint32_t BLb = sbase + SM_B_LO + b_lane;

        float be[8], bo[8];
#pragma unroll
        for (int nt = 0; nt < 8; nt++) {
            const int c = wn * 64 + (lid & 3) * 2 + nt * 8;
            be[nt] = bias[c];
            bo[nt] = bias[c + 1];
        }

        int t = blockIdx.x;
        for (int it = 0; t < NTILES; it++, t += GRID) {
            const int buf = it & 1;
            bar_sync(1 + buf, 512);                            // wait A[buf] ready

            const uint32_t AHb = sbase + (buf ? SM_A1_HI : SM_A0_HI) + a_lane;
            const uint32_t ALb = sbase + (buf ? SM_A1_LO : SM_A0_LO) + a_lane;

            float acc[2][8][4];
#pragma unroll
            for (int mt = 0; mt < 2; mt++)
#pragma unroll
                for (int nt = 0; nt < 8; nt++)
#pragma unroll
                    for (int e = 0; e < 4; e++) acc[mt][nt][e] = 0.0f;

            // merged k-loop: each fragment loaded once per k-step.
            // order: AH,BH -> AH*BH ; AL -> AL*BH ; BL (reuse b regs) -> AH*BL
#pragma unroll 2
            for (int ks = 0; ks < 8; ks++) {
                const uint32_t koff = ks * 32;
                uint32_t ah[2][4], al[2][4], b[4][4];
#pragma unroll
                for (int mt = 0; mt < 2; mt++)
                    ldsm_x4(ah[mt][0], ah[mt][1], ah[mt][2], ah[mt][3],
                            AHb + mt * (16 * PITCH) + koff);
#pragma unroll
                for (int nb = 0; nb < 4; nb++)
                    ldsm_x4(b[nb][0], b[nb][1], b[nb][2], b[nb][3],
                            BHb + nb * (16 * PITCH) + koff);
#pragma unroll
                for (int mt = 0; mt < 2; mt++)
#pragma unroll
                    for (int nb = 0; nb < 4; nb++) {
                        mma_bf16(acc[mt][nb * 2 + 0], ah[mt], b[nb][0], b[nb][2]);
                        mma_bf16(acc[mt][nb * 2 + 1], ah[mt], b[nb][1], b[nb][3]);
                    }
#pragma unroll
                for (int mt = 0; mt < 2; mt++)
                    ldsm_x4(al[mt][0], al[mt][1], al[mt][2], al[mt][3],
                            ALb + mt * (16 * PITCH) + koff);
#pragma unroll
                for (int mt = 0; mt < 2; mt++)
#pragma unroll
                    for (int nb = 0; nb < 4; nb++) {
                        mma_bf16(acc[mt][nb * 2 + 0], al[mt], b[nb][0], b[nb][2]);
                        mma_bf16(acc[mt][nb * 2 + 1], al[mt], b[nb][1], b[nb][3]);
                    }
#pragma unroll
                for (int nb = 0; nb < 4; nb++)
                    ldsm_x4(b[nb][0], b[nb][1], b[nb][2], b[nb][3],
                            BLb + nb * (16 * PITCH) + koff);
#pragma unroll
                for (int mt = 0; mt < 2; mt++)
#pragma unroll
                    for (int nb = 0; nb < 4; nb++) {
                        mma_bf16(acc[mt][nb * 2 + 0], ah[mt], b[nb][0], b[nb][2]);
                        mma_bf16(acc[mt][nb * 2 + 1], ah[mt], b[nb][1], b[nb][3]);
                    }
            }
            bar_arrive(3 + buf, 512);                          // A[buf] free

            // epilogue: bias + relu + direct float2 stores (overlaps producer)
            const int rbase = t * 64 + wm * 32 + (lid >> 2);
            const int cbase = wn * 64 + (lid & 3) * 2;
#pragma unroll
            for (int mt = 0; mt < 2; mt++) {
#pragma unroll
                for (int nt = 0; nt < 8; nt++) {
                    const int c = cbase + nt * 8;
                    float2 v0, v1;
                    v0.x = fmaxf(acc[mt][nt][0] + be[nt], 0.0f);
                    v0.y = fmaxf(acc[mt][nt][1] + bo[nt], 0.0f);
                    v1.x = fmaxf(acc[mt][nt][2] + be[nt], 0.0f);
                    v1.y = fmaxf(acc[mt][nt][3] + bo[nt], 0.0f);
                    const size_t r0 = (size_t)(rbase + mt * 16);
                    *(float2*)(out + r0 * 256 + c)       = v0;
                    *(float2*)(out + (r0 + 8) * 256 + c) = v1;
                }
            }
        }
    }
}

extern "C" void kernel_launch(void* const* d_in, const int* in_sizes, int n_in,
                              void* d_out, int out_size)
{
    const float* qpos  = (const float*)d_in[0];
    const float* qdir  = (const float*)d_in[1];
    const float* qab   = (const float*)d_in[2];
    const float* qcar  = (const float*)d_in[3];
    const float* qst   = (const float*)d_in[4];
    const float* apos  = (const float*)d_in[5];
    const float* adir  = (const float*)d_in[6];
    const float* aab   = (const float*)d_in[7];
    const float* acar  = (const float*)d_in[8];
    const float* ast   = (const float*)d_in[9];
    const int*   color = (const int*)  d_in[10];
    const float* W     = (const float*)d_in[11];
    const float* bias  = (const float*)d_in[12];
    float* out = (float*)d_out;

    w_split<<<128, 256>>>(W);

    cudaFuncSetAttribute(mg_enc_ws,
                         cudaFuncAttributeMaxDynamicSharedMemorySize, SMEM_BYTES);
    mg_enc_ws<<<GRID, NTHREADS, SMEM_BYTES>>>(
        qpos, qdir, qab, qcar, qst,
        apos, adir, aab, acar, ast,
        color, bias, out);
}